// round 1
// baseline (speedup 1.0000x reference)
#include <cuda_runtime.h>

// ---------------------------------------------------------------------------
// CausalSelfAttention: x[4,2048,1024] -> qkv -> causal MHA (16 heads, D=64,
// scale = C^-0.5 = 1/32) -> proj.  fp32 throughout (accuracy headroom vs 1e-3).
//
// Pipeline:
//   1) sgemm  : qkv[8192,3072] = x[8192,1024] @ w_attn[1024,3072]
//   2) attn   : flash-style causal attention per (b,h), writes y[B,T,C]
//   3) sgemm  : out[8192,1024] = y @ w_proj[1024,1024]
// Scratch in __device__ globals (allowed; no runtime allocation).
// ---------------------------------------------------------------------------

#define T_SEQ   2048
#define NEMB    1024
#define NHEADS  16
#define HEADD   64

__device__ float g_qkv[8192 * 3072];   // 96 MB scratch
__device__ float g_y  [8192 * 1024];   // 32 MB scratch

// ---------------------------------------------------------------------------
// SGEMM: C[M,N] = A[M,K] @ B[K,N], row-major, fp32.
// 128x128 block tile, BK=16, 256 threads, 8x8 per thread.
// All dims divide the tile sizes exactly for our shapes (no guards).
// ---------------------------------------------------------------------------
template <int M, int N, int K>
__global__ void __launch_bounds__(256) sgemm_kernel(const float* __restrict__ A,
                                                    const float* __restrict__ B,
                                                    float* __restrict__ C)
{
    constexpr int BM = 128, BN = 128, BK = 16;
    __shared__ float As[BK][BM + 4];   // transposed A tile, padded
    __shared__ float Bs[BK][BN];

    const int tid = threadIdx.x;
    const int bm  = blockIdx.y * BM;
    const int bn  = blockIdx.x * BN;
    const int tx  = tid & 15;
    const int ty  = tid >> 4;
    const int m0  = ty * 8;
    const int n0  = tx * 8;

    // load mappings
    const int aRow = tid >> 2;          // 0..63 (two iters -> 128 rows)
    const int aK   = (tid & 3) * 4;     // 0,4,8,12
    const int bRow = tid >> 5;          // 0..7 (two iters -> 16 rows)
    const int bCol = (tid & 31) * 4;    // 0..124

    float acc[8][8];
#pragma unroll
    for (int i = 0; i < 8; i++)
#pragma unroll
        for (int j = 0; j < 8; j++) acc[i][j] = 0.0f;

    for (int k0 = 0; k0 < K; k0 += BK) {
#pragma unroll
        for (int i = 0; i < 2; i++) {
            int r = aRow + i * 64;
            float4 a4 = *(const float4*)&A[(bm + r) * K + k0 + aK];
            As[aK + 0][r] = a4.x;
            As[aK + 1][r] = a4.y;
            As[aK + 2][r] = a4.z;
            As[aK + 3][r] = a4.w;
        }
#pragma unroll
        for (int i = 0; i < 2; i++) {
            int r = bRow + i * 8;
            *(float4*)&Bs[r][bCol] = *(const float4*)&B[(k0 + r) * N + bn + bCol];
        }
        __syncthreads();

#pragma unroll
        for (int kk = 0; kk < BK; kk++) {
            float a[8], b[8];
            *(float4*)&a[0] = *(const float4*)&As[kk][m0];
            *(float4*)&a[4] = *(const float4*)&As[kk][m0 + 4];
            *(float4*)&b[0] = *(const float4*)&Bs[kk][n0];
            *(float4*)&b[4] = *(const float4*)&Bs[kk][n0 + 4];
#pragma unroll
            for (int i = 0; i < 8; i++)
#pragma unroll
                for (int j = 0; j < 8; j++)
                    acc[i][j] = fmaf(a[i], b[j], acc[i][j]);
        }
        __syncthreads();
    }

#pragma unroll
    for (int i = 0; i < 8; i++) {
        float* c = &C[(bm + m0 + i) * N + bn + n0];
        *(float4*)(c)     = make_float4(acc[i][0], acc[i][1], acc[i][2], acc[i][3]);
        *(float4*)(c + 4) = make_float4(acc[i][4], acc[i][5], acc[i][6], acc[i][7]);
    }
}

// ---------------------------------------------------------------------------
// Flash attention (fp32), causal. One block = one (b,h) x 64-query tile.
// 256 threads; each thread owns a 4x4 subtile of S/O (64x64 tiles).
// Dynamic smem: Qs[d][i], Ks[d][j], Vs[j][d], Ps[j][i], each 64x68 floats.
// ---------------------------------------------------------------------------
__global__ void __launch_bounds__(256) attn_kernel(const float* __restrict__ qkv,
                                                   float* __restrict__ y)
{
    constexpr int BM = 64, BN = 64, D = 64;
    constexpr int LD = 68;                   // padded row stride (floats)
    constexpr int QS = 0;
    constexpr int KS = 64 * LD;              // 4352
    constexpr int VS = 2 * 64 * LD;          // 8704
    constexpr int PS = 3 * 64 * LD;          // 13056
    extern __shared__ float sm[];

    // reversed order: longest blocks (largest qb) launch first -> better tail
    const int qb = (int)gridDim.x - 1 - (int)blockIdx.x;   // query tile 0..31
    const int bh = blockIdx.y;
    const int b  = bh >> 4;
    const int h  = bh & 15;

    const int tid = threadIdx.x;
    const int tx  = tid & 15;
    const int ty  = tid >> 4;
    const int i0  = ty * 4;      // query-row base within tile
    const int j0  = tx * 4;      // key-col / out-dim base within tile

    const int rowStride = 3 * NEMB;          // 3072
    const float* qbase = qkv + (b * T_SEQ) * rowStride + h * HEADD;
    const float* kbase = qbase + NEMB;
    const float* vbase = qbase + 2 * NEMB;

    // cooperative load mapping: 4 lanes per row, each lane 16 consecutive floats
    const int lr = tid >> 2;                 // 0..63
    const int lc = (tid & 3) * 16;           // 0,16,32,48

    // ---- load Q tile (transposed, pre-scaled by C^-0.5 = 1/32) ----
    {
        const float* src = qbase + (qb * BM + lr) * rowStride + lc;
#pragma unroll
        for (int u = 0; u < 4; u++) {
            float4 v4 = *(const float4*)(src + u * 4);
            int c = lc + u * 4;
            sm[QS + (c + 0) * LD + lr] = v4.x * 0.03125f;
            sm[QS + (c + 1) * LD + lr] = v4.y * 0.03125f;
            sm[QS + (c + 2) * LD + lr] = v4.z * 0.03125f;
            sm[QS + (c + 3) * LD + lr] = v4.w * 0.03125f;
        }
    }

    float m_i[4], l_i[4], acc[4][4];
#pragma unroll
    for (int ii = 0; ii < 4; ii++) {
        m_i[ii] = -1e30f;
        l_i[ii] = 0.0f;
#pragma unroll
        for (int dd = 0; dd < 4; dd++) acc[ii][dd] = 0.0f;
    }

    const int ktiles = qb + 1;
    for (int kt = 0; kt < ktiles; kt++) {
        // ---- load K (transposed) and V tiles ----
        {
            const float* ksrc = kbase + (kt * BN + lr) * rowStride + lc;
            const float* vsrc = vbase + (kt * BN + lr) * rowStride + lc;
#pragma unroll
            for (int u = 0; u < 4; u++) {
                int c = lc + u * 4;
                float4 k4 = *(const float4*)(ksrc + u * 4);
                sm[KS + (c + 0) * LD + lr] = k4.x;
                sm[KS + (c + 1) * LD + lr] = k4.y;
                sm[KS + (c + 2) * LD + lr] = k4.z;
                sm[KS + (c + 3) * LD + lr] = k4.w;
                float4 v4 = *(const float4*)(vsrc + u * 4);
                *(float4*)&sm[VS + lr * LD + c] = v4;
            }
        }
        __syncthreads();   // also covers Q writes on first iteration

        // ---- S = Q K^T (4x4 per thread) ----
        float s[4][4];
#pragma unroll
        for (int ii = 0; ii < 4; ii++)
#pragma unroll
            for (int jj = 0; jj < 4; jj++) s[ii][jj] = 0.0f;

#pragma unroll 8
        for (int d = 0; d < D; d++) {
            float4 qa = *(const float4*)&sm[QS + d * LD + i0];
            float4 kb = *(const float4*)&sm[KS + d * LD + j0];
            float a[4] = {qa.x, qa.y, qa.z, qa.w};
            float bq[4] = {kb.x, kb.y, kb.z, kb.w};
#pragma unroll
            for (int ii = 0; ii < 4; ii++)
#pragma unroll
                for (int jj = 0; jj < 4; jj++)
                    s[ii][jj] = fmaf(a[ii], bq[jj], s[ii][jj]);
        }

        // ---- causal mask on the diagonal tile ----
        if (kt == qb) {
#pragma unroll
            for (int ii = 0; ii < 4; ii++)
#pragma unroll
                for (int jj = 0; jj < 4; jj++)
                    if (j0 + jj > i0 + ii) s[ii][jj] = -1e30f;
        }

        // ---- online softmax: row max -> alpha -> exp -> row sum ----
        float tmax[4], rs[4], alpha[4];
#pragma unroll
        for (int ii = 0; ii < 4; ii++) {
            float mx = s[ii][0];
            mx = fmaxf(mx, s[ii][1]);
            mx = fmaxf(mx, s[ii][2]);
            mx = fmaxf(mx, s[ii][3]);
            tmax[ii] = mx;
        }
#pragma unroll
        for (int o = 1; o < 16; o <<= 1)
#pragma unroll
            for (int ii = 0; ii < 4; ii++)
                tmax[ii] = fmaxf(tmax[ii], __shfl_xor_sync(0xffffffffu, tmax[ii], o));

#pragma unroll
        for (int ii = 0; ii < 4; ii++) {
            float mn = fmaxf(m_i[ii], tmax[ii]);
            alpha[ii] = __expf(m_i[ii] - mn);
            m_i[ii] = mn;
            rs[ii] = 0.0f;
        }
#pragma unroll
        for (int ii = 0; ii < 4; ii++)
#pragma unroll
            for (int jj = 0; jj < 4; jj++) {
                float p = __expf(s[ii][jj] - m_i[ii]);
                s[ii][jj] = p;
                rs[ii] += p;
            }
#pragma unroll
        for (int o = 1; o < 16; o <<= 1)
#pragma unroll
            for (int ii = 0; ii < 4; ii++)
                rs[ii] += __shfl_xor_sync(0xffffffffu, rs[ii], o);

#pragma unroll
        for (int ii = 0; ii < 4; ii++) {
            l_i[ii] = l_i[ii] * alpha[ii] + rs[ii];
#pragma unroll
            for (int dd = 0; dd < 4; dd++) acc[ii][dd] *= alpha[ii];
        }

        // ---- write P transposed: Ps[j][i] ----
#pragma unroll
        for (int jj = 0; jj < 4; jj++)
            *(float4*)&sm[PS + (j0 + jj) * LD + i0] =
                make_float4(s[0][jj], s[1][jj], s[2][jj], s[3][jj]);
        __syncthreads();

        // ---- O += P @ V : acc[ii][dd] over all j ----
#pragma unroll 8
        for (int j = 0; j < BN; j++) {
            float4 pa = *(const float4*)&sm[PS + j * LD + i0];
            float4 vb = *(const float4*)&sm[VS + j * LD + j0];
            float p[4] = {pa.x, pa.y, pa.z, pa.w};
            float v[4] = {vb.x, vb.y, vb.z, vb.w};
#pragma unroll
            for (int ii = 0; ii < 4; ii++)
#pragma unroll
                for (int dd = 0; dd < 4; dd++)
                    acc[ii][dd] = fmaf(p[ii], v[dd], acc[ii][dd]);
        }
        __syncthreads();   // protect Ks/Vs/Ps before next tile's loads
    }

    // ---- epilogue: O /= l, store to y[b, t, h*64 + d] ----
#pragma unroll
    for (int ii = 0; ii < 4; ii++) {
        float inv = 1.0f / l_i[ii];
        int t = qb * BM + i0 + ii;
        float* dst = y + (b * T_SEQ + t) * NEMB + h * HEADD + j0;
        *(float4*)dst = make_float4(acc[ii][0] * inv, acc[ii][1] * inv,
                                    acc[ii][2] * inv, acc[ii][3] * inv);
    }
}

// ---------------------------------------------------------------------------

extern "C" void kernel_launch(void* const* d_in, const int* in_sizes, int n_in,
                              void* d_out, int out_size)
{
    const float* x      = (const float*)d_in[0];   // [4,2048,1024]
    const float* w_attn = (const float*)d_in[1];   // [1024,3072]
    const float* w_proj = (const float*)d_in[2];   // [1024,1024]
    float* out = (float*)d_out;                    // [4,2048,1024]

    void* qkv_p = nullptr;
    void* y_p   = nullptr;
    cudaGetSymbolAddress(&qkv_p, g_qkv);
    cudaGetSymbolAddress(&y_p,   g_y);
    float* qkv = (float*)qkv_p;
    float* y   = (float*)y_p;

    const int SMEM_ATTN = 4 * 64 * 68 * (int)sizeof(float);   // 69632 B
    cudaFuncSetAttribute(attn_kernel,
                         cudaFuncAttributeMaxDynamicSharedMemorySize, SMEM_ATTN);

    // 1) qkv = x @ w_attn
    sgemm_kernel<8192, 3072, 1024><<<dim3(24, 64), 256>>>(x, w_attn, qkv);
    // 2) y = causal_attention(qkv)
    attn_kernel<<<dim3(32, 64), 256, SMEM_ATTN>>>(qkv, y);
    // 3) out = y @ w_proj
    sgemm_kernel<8192, 1024, 1024><<<dim3(8, 64), 256>>>(y, w_proj, out);
}

// round 3
// speedup vs baseline: 1.3600x; 1.3600x over previous
#include <cuda_runtime.h>
#include <cuda_bf16.h>
#include <cstdint>

// ---------------------------------------------------------------------------
// CausalSelfAttention on sm_100 (compute_100 PTX path -> no tcgen05; use
// mma.sync bf16 HMMA for the GEMMs):
//   1) split/transpose conversions (fp32 -> bf16 hi/lo pairs)
//   2) qkv = x @ w_attn   : mma.sync split-bf16 GEMM (3-pass, fp32 accum)
//   3) y   = causal attention (fp32 flash kernel), emits y as bf16 hi/lo
//   4) out = y @ w_proj   : same GEMM
// ---------------------------------------------------------------------------

#define T_SEQ   2048
#define NEMB    1024
#define NHEADS  16
#define HEADD   64
#define KDIM    1024

// ---------------- scratch (device globals; no runtime allocation) ----------
__device__ float         g_qkv[8192 * 3072];        // 96 MB
__device__ __nv_bfloat16 g_xhi[8192 * 1024];
__device__ __nv_bfloat16 g_xlo[8192 * 1024];
__device__ __nv_bfloat16 g_yhi[8192 * 1024];
__device__ __nv_bfloat16 g_ylo[8192 * 1024];
__device__ __nv_bfloat16 g_wahi[3072 * 1024];       // w_attn^T  [N,K]
__device__ __nv_bfloat16 g_walo[3072 * 1024];
__device__ __nv_bfloat16 g_wphi[1024 * 1024];       // w_proj^T  [N,K]
__device__ __nv_bfloat16 g_wplo[1024 * 1024];

// ---------------- PTX helpers (all sm_80-era; compile for compute_100) -----
__device__ __forceinline__ uint32_t smem_u32(const void* p) {
    uint32_t a;
    asm("{ .reg .u64 t; cvta.to.shared.u64 t, %1; cvt.u32.u64 %0, t; }"
        : "=r"(a) : "l"(p));
    return a;
}
__device__ __forceinline__ void cp_async16(uint32_t dst, const void* src) {
    asm volatile("cp.async.cg.shared.global [%0], [%1], 16;" :: "r"(dst), "l"(src));
}
__device__ __forceinline__ void cp_commit() {
    asm volatile("cp.async.commit_group;" ::: "memory");
}
template <int N>
__device__ __forceinline__ void cp_wait() {
    asm volatile("cp.async.wait_group %0;" :: "n"(N) : "memory");
}
__device__ __forceinline__ void ldmatrix_x4(uint32_t* r, uint32_t addr) {
    asm volatile("ldmatrix.sync.aligned.m8n8.x4.shared.b16 {%0,%1,%2,%3}, [%4];"
                 : "=r"(r[0]), "=r"(r[1]), "=r"(r[2]), "=r"(r[3]) : "r"(addr));
}
__device__ __forceinline__ void mma_bf16(float* d, const uint32_t* a, const uint32_t* b) {
    asm volatile(
        "mma.sync.aligned.m16n8k16.row.col.f32.bf16.bf16.f32 "
        "{%0,%1,%2,%3}, {%4,%5,%6,%7}, {%8,%9}, {%0,%1,%2,%3};"
        : "+f"(d[0]), "+f"(d[1]), "+f"(d[2]), "+f"(d[3])
        : "r"(a[0]), "r"(a[1]), "r"(a[2]), "r"(a[3]), "r"(b[0]), "r"(b[1]));
}

// ---------------------------------------------------------------------------
// split-bf16 GEMM: C[M,N](fp32) = (Ahi+Alo)[M,K] @ (Bhi+Blo)[N,K]^T
// CTA 128x128, BK=32, 256 threads (8 warps, 2x4), warp tile 64x32.
// Smem rows: 32 bf16 data + 16B pad = 80B stride (conflict-free ldmatrix).
// 2-stage cp.async pipeline. K=1024. grid = (N/128, M/128).
// ---------------------------------------------------------------------------
#define G_LDS    80                     // smem row stride (bytes)
#define OFF_AHI  0
#define OFF_ALO  10240
#define OFF_BHI  20480
#define OFF_BLO  30720
#define G_STAGE  40960
#define GEMM_SMEM (2 * G_STAGE)

__device__ __forceinline__ void gemm_load_stage(
    uint32_t sb,
    const __nv_bfloat16* __restrict__ Ahi, const __nv_bfloat16* __restrict__ Alo,
    const __nv_bfloat16* __restrict__ Bhi, const __nv_bfloat16* __restrict__ Blo,
    int bm, int bn, int k0, int tid)
{
#pragma unroll
    for (int i = 0; i < 2; i++) {
        int idx = tid + i * 256;          // 0..511 : 128 rows x 4 chunks
        int r = idx >> 2, c = idx & 3;
        uint32_t off = (uint32_t)(r * G_LDS + c * 16);
        size_t gA = (size_t)(bm + r) * KDIM + k0 + c * 8;
        size_t gB = (size_t)(bn + r) * KDIM + k0 + c * 8;
        cp_async16(sb + OFF_AHI + off, Ahi + gA);
        cp_async16(sb + OFF_ALO + off, Alo + gA);
        cp_async16(sb + OFF_BHI + off, Bhi + gB);
        cp_async16(sb + OFF_BLO + off, Blo + gB);
    }
    cp_commit();
}

__global__ void __launch_bounds__(256) gemm_mma_kernel(
    const __nv_bfloat16* __restrict__ Ahi, const __nv_bfloat16* __restrict__ Alo,
    const __nv_bfloat16* __restrict__ Bhi, const __nv_bfloat16* __restrict__ Blo,
    float* __restrict__ C, int N)
{
    extern __shared__ char smem[];
    const uint32_t sbase = smem_u32(smem);

    const int tid  = threadIdx.x;
    const int lane = tid & 31;
    const int wid  = tid >> 5;
    const int bm   = blockIdx.y * 128;
    const int bn   = blockIdx.x * 128;
    const int wm   = (wid >> 2) * 64;     // 0 / 64
    const int wn   = (wid & 3) * 32;      // 0/32/64/96

    float acc[4][4][4];
#pragma unroll
    for (int mi = 0; mi < 4; mi++)
#pragma unroll
        for (int ni = 0; ni < 4; ni++)
#pragma unroll
            for (int q = 0; q < 4; q++) acc[mi][ni][q] = 0.0f;

    // ldmatrix address offsets (within a matrix region)
    const uint32_t a_off = (uint32_t)((lane & 15) * G_LDS + (lane >> 4) * 16);
    const uint32_t b_off = a_off;   // same shape for the 16-row B x4 loads

    gemm_load_stage(sbase,           Ahi, Alo, Bhi, Blo, bm, bn, 0,  tid);
    gemm_load_stage(sbase + G_STAGE, Ahi, Alo, Bhi, Blo, bm, bn, 32, tid);

    const int nk = KDIM / 32;   // 32 iterations
    for (int it = 0; it < nk; it++) {
        const uint32_t sb = sbase + (uint32_t)(it & 1) * G_STAGE;

        if (it < nk - 1) cp_wait<1>(); else cp_wait<0>();
        __syncthreads();

#pragma unroll
        for (int ks = 0; ks < 2; ks++) {
            const uint32_t kcol = (uint32_t)(ks * 32);

            uint32_t bhi[4][2], blo[4][2];
#pragma unroll
            for (int pair = 0; pair < 2; pair++) {
                uint32_t r4[4];
                uint32_t addr = sb + OFF_BHI +
                                (uint32_t)((wn + pair * 16) * G_LDS) + kcol + b_off;
                ldmatrix_x4(r4, addr);
                bhi[pair * 2 + 0][0] = r4[0]; bhi[pair * 2 + 1][0] = r4[1];
                bhi[pair * 2 + 0][1] = r4[2]; bhi[pair * 2 + 1][1] = r4[3];
                addr = sb + OFF_BLO +
                       (uint32_t)((wn + pair * 16) * G_LDS) + kcol + b_off;
                ldmatrix_x4(r4, addr);
                blo[pair * 2 + 0][0] = r4[0]; blo[pair * 2 + 1][0] = r4[1];
                blo[pair * 2 + 0][1] = r4[2]; blo[pair * 2 + 1][1] = r4[3];
            }

#pragma unroll
            for (int mi = 0; mi < 4; mi++) {
                uint32_t ahi[4], alo[4];
                uint32_t addr = sb + OFF_AHI +
                                (uint32_t)((wm + mi * 16) * G_LDS) + kcol + a_off;
                ldmatrix_x4(ahi, addr);
                addr = sb + OFF_ALO +
                       (uint32_t)((wm + mi * 16) * G_LDS) + kcol + a_off;
                ldmatrix_x4(alo, addr);
#pragma unroll
                for (int ni = 0; ni < 4; ni++) {
                    mma_bf16(acc[mi][ni], ahi, bhi[ni]);   // hi*hi
                    mma_bf16(acc[mi][ni], alo, bhi[ni]);   // lo*hi
                    mma_bf16(acc[mi][ni], ahi, blo[ni]);   // hi*lo
                }
            }
        }
        __syncthreads();

        if (it + 2 < nk)
            gemm_load_stage(sb, Ahi, Alo, Bhi, Blo, bm, bn, (it + 2) * 32, tid);
    }

    // epilogue: acc -> C
    const int row_base = bm + wm + (lane >> 2);
    const int col_base = bn + wn + (lane & 3) * 2;
#pragma unroll
    for (int mi = 0; mi < 4; mi++) {
#pragma unroll
        for (int ni = 0; ni < 4; ni++) {
            int r0 = row_base + mi * 16;
            int cc = col_base + ni * 8;
            *(float2*)&C[(size_t)r0 * N + cc] =
                make_float2(acc[mi][ni][0], acc[mi][ni][1]);
            *(float2*)&C[(size_t)(r0 + 8) * N + cc] =
                make_float2(acc[mi][ni][2], acc[mi][ni][3]);
        }
    }
}

// ---------------------------------------------------------------------------
// fp32 -> bf16 hi/lo split (elementwise, float4 vectorized)
// ---------------------------------------------------------------------------
__global__ void __launch_bounds__(256) split_kernel(const float* __restrict__ in,
                                                    __nv_bfloat16* __restrict__ hi,
                                                    __nv_bfloat16* __restrict__ lo,
                                                    int n4)
{
    int i = blockIdx.x * 256 + threadIdx.x;
    if (i >= n4) return;
    float4 v = ((const float4*)in)[i];
    float vv[4] = {v.x, v.y, v.z, v.w};
    __nv_bfloat16 h[4], l[4];
#pragma unroll
    for (int q = 0; q < 4; q++) {
        h[q] = __float2bfloat16(vv[q]);
        l[q] = __float2bfloat16(vv[q] - __bfloat162float(h[q]));
    }
    ((__nv_bfloat162*)hi)[i * 2 + 0] = __nv_bfloat162(h[0], h[1]);
    ((__nv_bfloat162*)hi)[i * 2 + 1] = __nv_bfloat162(h[2], h[3]);
    ((__nv_bfloat162*)lo)[i * 2 + 0] = __nv_bfloat162(l[0], l[1]);
    ((__nv_bfloat162*)lo)[i * 2 + 1] = __nv_bfloat162(l[2], l[3]);
}

// ---------------------------------------------------------------------------
// transpose + split: in[K,N] fp32 row-major -> hi/lo[N,K] bf16 row-major
// ---------------------------------------------------------------------------
__global__ void __launch_bounds__(256) tsplit_kernel(const float* __restrict__ in,
                                                     __nv_bfloat16* __restrict__ hi,
                                                     __nv_bfloat16* __restrict__ lo,
                                                     int K, int N)
{
    __shared__ float t[32][33];
    const int tx = threadIdx.x, ty = threadIdx.y;
    const int x  = blockIdx.x * 32 + tx;        // N index (read)
    const int y0 = blockIdx.y * 32;             // K base
#pragma unroll
    for (int j = 0; j < 32; j += 8)
        t[ty + j][tx] = in[(size_t)(y0 + ty + j) * N + x];
    __syncthreads();
#pragma unroll
    for (int j = 0; j < 32; j += 8) {
        float v = t[tx][ty + j];
        int nIdx = blockIdx.x * 32 + ty + j;
        int kIdx = y0 + tx;
        __nv_bfloat16 h = __float2bfloat16(v);
        __nv_bfloat16 l = __float2bfloat16(v - __bfloat162float(h));
        hi[(size_t)nIdx * K + kIdx] = h;
        lo[(size_t)nIdx * K + kIdx] = l;
    }
}

// ---------------------------------------------------------------------------
// Flash attention (fp32), causal — epilogue emits y as bf16 hi/lo.
// ---------------------------------------------------------------------------
__global__ void __launch_bounds__(256) attn_kernel(const float* __restrict__ qkv,
                                                   __nv_bfloat16* __restrict__ yhi,
                                                   __nv_bfloat16* __restrict__ ylo)
{
    constexpr int BM = 64, BN = 64, D = 64;
    constexpr int LD = 68;
    constexpr int QS = 0;
    constexpr int KS = 64 * LD;
    constexpr int VS = 2 * 64 * LD;
    constexpr int PS = 3 * 64 * LD;
    extern __shared__ float sm[];

    const int qb = (int)gridDim.x - 1 - (int)blockIdx.x;
    const int bh = blockIdx.y;
    const int b  = bh >> 4;
    const int h  = bh & 15;

    const int tid = threadIdx.x;
    const int tx  = tid & 15;
    const int ty  = tid >> 4;
    const int i0  = ty * 4;
    const int j0  = tx * 4;

    const int rowStride = 3 * NEMB;
    const float* qbase = qkv + (size_t)(b * T_SEQ) * rowStride + h * HEADD;
    const float* kbase = qbase + NEMB;
    const float* vbase = qbase + 2 * NEMB;

    const int lr = tid >> 2;
    const int lc = (tid & 3) * 16;

    {
        const float* src = qbase + (size_t)(qb * BM + lr) * rowStride + lc;
#pragma unroll
        for (int u = 0; u < 4; u++) {
            float4 v4 = *(const float4*)(src + u * 4);
            int c = lc + u * 4;
            sm[QS + (c + 0) * LD + lr] = v4.x * 0.03125f;
            sm[QS + (c + 1) * LD + lr] = v4.y * 0.03125f;
            sm[QS + (c + 2) * LD + lr] = v4.z * 0.03125f;
            sm[QS + (c + 3) * LD + lr] = v4.w * 0.03125f;
        }
    }

    float m_i[4], l_i[4], acc[4][4];
#pragma unroll
    for (int ii = 0; ii < 4; ii++) {
        m_i[ii] = -1e30f;
        l_i[ii] = 0.0f;
#pragma unroll
        for (int dd = 0; dd < 4; dd++) acc[ii][dd] = 0.0f;
    }

    const int ktiles = qb + 1;
    for (int kt = 0; kt < ktiles; kt++) {
        {
            const float* ksrc = kbase + (size_t)(kt * BN + lr) * rowStride + lc;
            const float* vsrc = vbase + (size_t)(kt * BN + lr) * rowStride + lc;
#pragma unroll
            for (int u = 0; u < 4; u++) {
                int c = lc + u * 4;
                float4 k4 = *(const float4*)(ksrc + u * 4);
                sm[KS + (c + 0) * LD + lr] = k4.x;
                sm[KS + (c + 1) * LD + lr] = k4.y;
                sm[KS + (c + 2) * LD + lr] = k4.z;
                sm[KS + (c + 3) * LD + lr] = k4.w;
                float4 v4 = *(const float4*)(vsrc + u * 4);
                *(float4*)&sm[VS + lr * LD + c] = v4;
            }
        }
        __syncthreads();

        float s[4][4];
#pragma unroll
        for (int ii = 0; ii < 4; ii++)
#pragma unroll
            for (int jj = 0; jj < 4; jj++) s[ii][jj] = 0.0f;

#pragma unroll 8
        for (int d = 0; d < D; d++) {
            float4 qa = *(const float4*)&sm[QS + d * LD + i0];
            float4 kb = *(const float4*)&sm[KS + d * LD + j0];
            float a[4] = {qa.x, qa.y, qa.z, qa.w};
            float bq[4] = {kb.x, kb.y, kb.z, kb.w};
#pragma unroll
            for (int ii = 0; ii < 4; ii++)
#pragma unroll
                for (int jj = 0; jj < 4; jj++)
                    s[ii][jj] = fmaf(a[ii], bq[jj], s[ii][jj]);
        }

        if (kt == qb) {
#pragma unroll
            for (int ii = 0; ii < 4; ii++)
#pragma unroll
                for (int jj = 0; jj < 4; jj++)
                    if (j0 + jj > i0 + ii) s[ii][jj] = -1e30f;
        }

        float tmax[4], rs[4], alpha[4];
#pragma unroll
        for (int ii = 0; ii < 4; ii++)
            tmax[ii] = fmaxf(fmaxf(s[ii][0], s[ii][1]), fmaxf(s[ii][2], s[ii][3]));
#pragma unroll
        for (int o = 1; o < 16; o <<= 1)
#pragma unroll
            for (int ii = 0; ii < 4; ii++)
                tmax[ii] = fmaxf(tmax[ii], __shfl_xor_sync(0xffffffffu, tmax[ii], o));

#pragma unroll
        for (int ii = 0; ii < 4; ii++) {
            float mn = fmaxf(m_i[ii], tmax[ii]);
            alpha[ii] = __expf(m_i[ii] - mn);
            m_i[ii] = mn;
            rs[ii] = 0.0f;
        }
#pragma unroll
        for (int ii = 0; ii < 4; ii++)
#pragma unroll
            for (int jj = 0; jj < 4; jj++) {
                float p = __expf(s[ii][jj] - m_i[ii]);
                s[ii][jj] = p;
                rs[ii] += p;
            }
#pragma unroll
        for (int o = 1; o < 16; o <<= 1)
#pragma unroll
            for (int ii = 0; ii < 4; ii++)
                rs[ii] += __shfl_xor_sync(0xffffffffu, rs[ii], o);

#pragma unroll
        for (int ii = 0; ii < 4; ii++) {
            l_i[ii] = l_i[ii] * alpha[ii] + rs[ii];
#pragma unroll
            for (int dd = 0; dd < 4; dd++) acc[ii][dd] *= alpha[ii];
        }

#pragma unroll
        for (int jj = 0; jj < 4; jj++)
            *(float4*)&sm[PS + (j0 + jj) * LD + i0] =
                make_float4(s[0][jj], s[1][jj], s[2][jj], s[3][jj]);
        __syncthreads();

#pragma unroll 8
        for (int j = 0; j < BN; j++) {
            float4 pa = *(const float4*)&sm[PS + j * LD + i0];
            float4 vb = *(const float4*)&sm[VS + j * LD + j0];
            float p[4] = {pa.x, pa.y, pa.z, pa.w};
            float v[4] = {vb.x, vb.y, vb.z, vb.w};
#pragma unroll
            for (int ii = 0; ii < 4; ii++)
#pragma unroll
                for (int dd = 0; dd < 4; dd++)
                    acc[ii][dd] = fmaf(p[ii], v[dd], acc[ii][dd]);
        }
        __syncthreads();
    }

    // epilogue: O /= l, emit bf16 hi/lo split for the proj GEMM
#pragma unroll
    for (int ii = 0; ii < 4; ii++) {
        float inv = 1.0f / l_i[ii];
        int t = qb * BM + i0 + ii;
        size_t base = (size_t)(b * T_SEQ + t) * NEMB + h * HEADD + j0;
        __nv_bfloat16 hh[4], ll[4];
#pragma unroll
        for (int dd = 0; dd < 4; dd++) {
            float v = acc[ii][dd] * inv;
            hh[dd] = __float2bfloat16(v);
            ll[dd] = __float2bfloat16(v - __bfloat162float(hh[dd]));
        }
        *(__nv_bfloat162*)(yhi + base)     = __nv_bfloat162(hh[0], hh[1]);
        *(__nv_bfloat162*)(yhi + base + 2) = __nv_bfloat162(hh[2], hh[3]);
        *(__nv_bfloat162*)(ylo + base)     = __nv_bfloat162(ll[0], ll[1]);
        *(__nv_bfloat162*)(ylo + base + 2) = __nv_bfloat162(ll[2], ll[3]);
    }
}

// ---------------------------------------------------------------------------

extern "C" void kernel_launch(void* const* d_in, const int* in_sizes, int n_in,
                              void* d_out, int out_size)
{
    const float* x      = (const float*)d_in[0];   // [4,2048,1024]
    const float* w_attn = (const float*)d_in[1];   // [1024,3072]
    const float* w_proj = (const float*)d_in[2];   // [1024,1024]
    float* out = (float*)d_out;                    // [4,2048,1024]

    void *qkv_p, *xhi_p, *xlo_p, *yhi_p, *ylo_p, *wahi_p, *walo_p, *wphi_p, *wplo_p;
    cudaGetSymbolAddress(&qkv_p,  g_qkv);
    cudaGetSymbolAddress(&xhi_p,  g_xhi);
    cudaGetSymbolAddress(&xlo_p,  g_xlo);
    cudaGetSymbolAddress(&yhi_p,  g_yhi);
    cudaGetSymbolAddress(&ylo_p,  g_ylo);
    cudaGetSymbolAddress(&wahi_p, g_wahi);
    cudaGetSymbolAddress(&walo_p, g_walo);
    cudaGetSymbolAddress(&wphi_p, g_wphi);
    cudaGetSymbolAddress(&wplo_p, g_wplo);

    float* qkv = (float*)qkv_p;
    __nv_bfloat16* xhi  = (__nv_bfloat16*)xhi_p;
    __nv_bfloat16* xlo  = (__nv_bfloat16*)xlo_p;
    __nv_bfloat16* yhi  = (__nv_bfloat16*)yhi_p;
    __nv_bfloat16* ylo  = (__nv_bfloat16*)ylo_p;
    __nv_bfloat16* wahi = (__nv_bfloat16*)wahi_p;
    __nv_bfloat16* walo = (__nv_bfloat16*)walo_p;
    __nv_bfloat16* wphi = (__nv_bfloat16*)wphi_p;
    __nv_bfloat16* wplo = (__nv_bfloat16*)wplo_p;

    cudaFuncSetAttribute(gemm_mma_kernel,
                         cudaFuncAttributeMaxDynamicSharedMemorySize, GEMM_SMEM);
    const int SMEM_ATTN = 4 * 64 * 68 * (int)sizeof(float);
    cudaFuncSetAttribute(attn_kernel,
                         cudaFuncAttributeMaxDynamicSharedMemorySize, SMEM_ATTN);

    // conversions
    split_kernel<<<(8192 * 1024 / 4 + 255) / 256, 256>>>(x, xhi, xlo, 8192 * 1024 / 4);
    tsplit_kernel<<<dim3(3072 / 32, 1024 / 32), dim3(32, 8)>>>(w_attn, wahi, walo, 1024, 3072);
    tsplit_kernel<<<dim3(1024 / 32, 1024 / 32), dim3(32, 8)>>>(w_proj, wphi, wplo, 1024, 1024);

    // 1) qkv = x @ w_attn   (M=8192, N=3072)
    gemm_mma_kernel<<<dim3(3072 / 128, 8192 / 128), 256, GEMM_SMEM>>>(
        xhi, xlo, wahi, walo, qkv, 3072);

    // 2) y = causal attention(qkv) -> bf16 hi/lo
    attn_kernel<<<dim3(32, 64), 256, SMEM_ATTN>>>(qkv, yhi, ylo);

    // 3) out = y @ w_proj   (M=8192, N=1024)
    gemm_mma_kernel<<<dim3(1024 / 128, 8192 / 128), 256, GEMM_SMEM>>>(
        yhi, ylo, wphi, wplo, out, 1024);
}

// round 6
// speedup vs baseline: 2.4200x; 1.7794x over previous
#include <cuda_runtime.h>
#include <cuda_bf16.h>
#include <cstdint>

// ---------------------------------------------------------------------------
// CausalSelfAttention, all matmuls on mma.sync bf16 (3-pass hi/lo split,
// fp32 accum => fp32-grade accuracy):
//   1) conversions: x -> hi/lo, weights -> transposed hi/lo
//   2) qkv = x @ w_attn   (epilogue writes qkv as bf16 hi/lo)
//   3) flash attention on tensor cores (QK^T and P@V split 3-pass)
//   4) out = y @ w_proj
// ---------------------------------------------------------------------------

#define T_SEQ   2048
#define NEMB    1024
#define KDIM    1024

// ---------------- scratch ---------------------------------------------------
__device__ __nv_bfloat16 g_qkvhi[8192 * 3072];
__device__ __nv_bfloat16 g_qkvlo[8192 * 3072];
__device__ __nv_bfloat16 g_xhi[8192 * 1024];
__device__ __nv_bfloat16 g_xlo[8192 * 1024];
__device__ __nv_bfloat16 g_yhi[8192 * 1024];
__device__ __nv_bfloat16 g_ylo[8192 * 1024];
__device__ __nv_bfloat16 g_wahi[3072 * 1024];
__device__ __nv_bfloat16 g_walo[3072 * 1024];
__device__ __nv_bfloat16 g_wphi[1024 * 1024];
__device__ __nv_bfloat16 g_wplo[1024 * 1024];

// ---------------- PTX helpers ----------------------------------------------
__device__ __forceinline__ uint32_t smem_u32(const void* p) {
    uint32_t a;
    asm("{ .reg .u64 t; cvta.to.shared.u64 t, %1; cvt.u32.u64 %0, t; }"
        : "=r"(a) : "l"(p));
    return a;
}
__device__ __forceinline__ void cp_async16(uint32_t dst, const void* src) {
    asm volatile("cp.async.cg.shared.global [%0], [%1], 16;" :: "r"(dst), "l"(src));
}
__device__ __forceinline__ void cp_commit() {
    asm volatile("cp.async.commit_group;" ::: "memory");
}
template <int N>
__device__ __forceinline__ void cp_wait() {
    asm volatile("cp.async.wait_group %0;" :: "n"(N) : "memory");
}
__device__ __forceinline__ void ldmatrix_x4(uint32_t* r, uint32_t addr) {
    asm volatile("ldmatrix.sync.aligned.m8n8.x4.shared.b16 {%0,%1,%2,%3}, [%4];"
                 : "=r"(r[0]), "=r"(r[1]), "=r"(r[2]), "=r"(r[3]) : "r"(addr));
}
__device__ __forceinline__ void ldmatrix_x4_t(uint32_t* r, uint32_t addr) {
    asm volatile("ldmatrix.sync.aligned.m8n8.x4.trans.shared.b16 {%0,%1,%2,%3}, [%4];"
                 : "=r"(r[0]), "=r"(r[1]), "=r"(r[2]), "=r"(r[3]) : "r"(addr));
}
__device__ __forceinline__ void mma_bf16(float* d, const uint32_t* a, const uint32_t* b) {
    asm volatile(
        "mma.sync.aligned.m16n8k16.row.col.f32.bf16.bf16.f32 "
        "{%0,%1,%2,%3}, {%4,%5,%6,%7}, {%8,%9}, {%0,%1,%2,%3};"
        : "+f"(d[0]), "+f"(d[1]), "+f"(d[2]), "+f"(d[3])
        : "r"(a[0]), "r"(a[1]), "r"(a[2]), "r"(a[3]), "r"(b[0]), "r"(b[1]));
}

// ---------------------------------------------------------------------------
// split-bf16 GEMM: C[M,N] = (Ahi+Alo)[M,K] @ (Bhi+Blo)[N,K]^T, 3-pass.
// CTA 128x128, BK=32, 256 threads, 2 CTAs/SM. SPLIT=1 -> write bf16 hi/lo.
// ---------------------------------------------------------------------------
#define G_LDS    80
#define OFF_AHI  0
#define OFF_ALO  10240
#define OFF_BHI  20480
#define OFF_BLO  30720
#define G_STAGE  40960
#define GEMM_SMEM (2 * G_STAGE)

__device__ __forceinline__ void gemm_load_stage(
    uint32_t sb,
    const __nv_bfloat16* __restrict__ Ahi, const __nv_bfloat16* __restrict__ Alo,
    const __nv_bfloat16* __restrict__ Bhi, const __nv_bfloat16* __restrict__ Blo,
    int bm, int bn, int k0, int tid)
{
#pragma unroll
    for (int i = 0; i < 2; i++) {
        int idx = tid + i * 256;
        int r = idx >> 2, c = idx & 3;
        uint32_t off = (uint32_t)(r * G_LDS + c * 16);
        size_t gA = (size_t)(bm + r) * KDIM + k0 + c * 8;
        size_t gB = (size_t)(bn + r) * KDIM + k0 + c * 8;
        cp_async16(sb + OFF_AHI + off, Ahi + gA);
        cp_async16(sb + OFF_ALO + off, Alo + gA);
        cp_async16(sb + OFF_BHI + off, Bhi + gB);
        cp_async16(sb + OFF_BLO + off, Blo + gB);
    }
    cp_commit();
}

template <int SPLIT>
__global__ void __launch_bounds__(256, 2) gemm_mma_kernel(
    const __nv_bfloat16* __restrict__ Ahi, const __nv_bfloat16* __restrict__ Alo,
    const __nv_bfloat16* __restrict__ Bhi, const __nv_bfloat16* __restrict__ Blo,
    float* __restrict__ Cf,
    __nv_bfloat16* __restrict__ Chi, __nv_bfloat16* __restrict__ Clo, int N)
{
    extern __shared__ char smem[];
    const uint32_t sbase = smem_u32(smem);

    const int tid  = threadIdx.x;
    const int lane = tid & 31;
    const int wid  = tid >> 5;
    const int bm   = blockIdx.y * 128;
    const int bn   = blockIdx.x * 128;
    const int wm   = (wid >> 2) * 64;
    const int wn   = (wid & 3) * 32;

    float acc[4][4][4];
#pragma unroll
    for (int mi = 0; mi < 4; mi++)
#pragma unroll
        for (int ni = 0; ni < 4; ni++)
#pragma unroll
            for (int q = 0; q < 4; q++) acc[mi][ni][q] = 0.0f;

    const uint32_t lm_off = (uint32_t)((lane & 15) * G_LDS + (lane >> 4) * 16);

    gemm_load_stage(sbase,           Ahi, Alo, Bhi, Blo, bm, bn, 0,  tid);
    gemm_load_stage(sbase + G_STAGE, Ahi, Alo, Bhi, Blo, bm, bn, 32, tid);

    const int nk = KDIM / 32;
    for (int it = 0; it < nk; it++) {
        const uint32_t sb = sbase + (uint32_t)(it & 1) * G_STAGE;

        if (it < nk - 1) cp_wait<1>(); else cp_wait<0>();
        __syncthreads();

#pragma unroll
        for (int ks = 0; ks < 2; ks++) {
            const uint32_t kcol = (uint32_t)(ks * 32);

            uint32_t bhi[4][2], blo[4][2];
#pragma unroll
            for (int pair = 0; pair < 2; pair++) {
                uint32_t r4[4];
                ldmatrix_x4(r4, sb + OFF_BHI +
                            (uint32_t)((wn + pair * 16) * G_LDS) + kcol + lm_off);
                bhi[pair * 2 + 0][0] = r4[0]; bhi[pair * 2 + 1][0] = r4[1];
                bhi[pair * 2 + 0][1] = r4[2]; bhi[pair * 2 + 1][1] = r4[3];
                ldmatrix_x4(r4, sb + OFF_BLO +
                            (uint32_t)((wn + pair * 16) * G_LDS) + kcol + lm_off);
                blo[pair * 2 + 0][0] = r4[0]; blo[pair * 2 + 1][0] = r4[1];
                blo[pair * 2 + 0][1] = r4[2]; blo[pair * 2 + 1][1] = r4[3];
            }

#pragma unroll
            for (int mi = 0; mi < 4; mi++) {
                uint32_t ahi[4], alo[4];
                ldmatrix_x4(ahi, sb + OFF_AHI +
                            (uint32_t)((wm + mi * 16) * G_LDS) + kcol + lm_off);
                ldmatrix_x4(alo, sb + OFF_ALO +
                            (uint32_t)((wm + mi * 16) * G_LDS) + kcol + lm_off);
#pragma unroll
                for (int ni = 0; ni < 4; ni++) mma_bf16(acc[mi][ni], ahi, bhi[ni]);
#pragma unroll
                for (int ni = 0; ni < 4; ni++) mma_bf16(acc[mi][ni], alo, bhi[ni]);
#pragma unroll
                for (int ni = 0; ni < 4; ni++) mma_bf16(acc[mi][ni], ahi, blo[ni]);
            }
        }
        __syncthreads();

        if (it + 2 < nk)
            gemm_load_stage(sb, Ahi, Alo, Bhi, Blo, bm, bn, (it + 2) * 32, tid);
    }

    const int row_base = bm + wm + (lane >> 2);
    const int col_base = bn + wn + (lane & 3) * 2;
#pragma unroll
    for (int mi = 0; mi < 4; mi++) {
#pragma unroll
        for (int ni = 0; ni < 4; ni++) {
            int cc = col_base + ni * 8;
#pragma unroll
            for (int half = 0; half < 2; half++) {
                int r = row_base + mi * 16 + half * 8;
                float v0 = acc[mi][ni][half * 2 + 0];
                float v1 = acc[mi][ni][half * 2 + 1];
                if (SPLIT) {
                    __nv_bfloat162 h2 = __floats2bfloat162_rn(v0, v1);
                    __nv_bfloat162 l2 = __floats2bfloat162_rn(
                        v0 - __bfloat162float(h2.x), v1 - __bfloat162float(h2.y));
                    *(__nv_bfloat162*)&Chi[(size_t)r * N + cc] = h2;
                    *(__nv_bfloat162*)&Clo[(size_t)r * N + cc] = l2;
                } else {
                    *(float2*)&Cf[(size_t)r * N + cc] = make_float2(v0, v1);
                }
            }
        }
    }
}

// ---------------------------------------------------------------------------
// conversions
// ---------------------------------------------------------------------------
__global__ void __launch_bounds__(256) split_kernel(const float* __restrict__ in,
                                                    __nv_bfloat16* __restrict__ hi,
                                                    __nv_bfloat16* __restrict__ lo,
                                                    int n4)
{
    int i = blockIdx.x * 256 + threadIdx.x;
    if (i >= n4) return;
    float4 v = ((const float4*)in)[i];
    float vv[4] = {v.x, v.y, v.z, v.w};
    __nv_bfloat16 h[4], l[4];
#pragma unroll
    for (int q = 0; q < 4; q++) {
        h[q] = __float2bfloat16(vv[q]);
        l[q] = __float2bfloat16(vv[q] - __bfloat162float(h[q]));
    }
    ((__nv_bfloat162*)hi)[i * 2 + 0] = __nv_bfloat162(h[0], h[1]);
    ((__nv_bfloat162*)hi)[i * 2 + 1] = __nv_bfloat162(h[2], h[3]);
    ((__nv_bfloat162*)lo)[i * 2 + 0] = __nv_bfloat162(l[0], l[1]);
    ((__nv_bfloat162*)lo)[i * 2 + 1] = __nv_bfloat162(l[2], l[3]);
}

__global__ void __launch_bounds__(256) tsplit_kernel(const float* __restrict__ in,
                                                     __nv_bfloat16* __restrict__ hi,
                                                     __nv_bfloat16* __restrict__ lo,
                                                     int K, int N)
{
    __shared__ float t[32][33];
    const int tx = threadIdx.x, ty = threadIdx.y;
    const int x  = blockIdx.x * 32 + tx;
    const int y0 = blockIdx.y * 32;
#pragma unroll
    for (int j = 0; j < 32; j += 8)
        t[ty + j][tx] = in[(size_t)(y0 + ty + j) * N + x];
    __syncthreads();
#pragma unroll
    for (int j = 0; j < 32; j += 8) {
        float v = t[tx][ty + j];
        int nIdx = blockIdx.x * 32 + ty + j;
        int kIdx = y0 + tx;
        __nv_bfloat16 h = __float2bfloat16(v);
        __nv_bfloat16 l = __float2bfloat16(v - __bfloat162float(h));
        hi[(size_t)nIdx * K + kIdx] = h;
        lo[(size_t)nIdx * K + kIdx] = l;
    }
}

// ---------------------------------------------------------------------------
// Tensor-core flash attention, causal. 128 threads (4 warps); one block =
// one (b,h) x 64-query tile. All matmuls split-bf16 3-pass, fp32 accum.
// Smem tiles: rows of 64 bf16, stride 72 bf16 (144B).
// ---------------------------------------------------------------------------
#define A_LDS   144                     // bytes per row
#define A_TILE  (64 * A_LDS)            // 9216 B
#define AQ_HI   0
#define AQ_LO   A_TILE
#define A_ST0   (2 * A_TILE)            // stage base
#define A_KHI   0
#define A_KLO   A_TILE
#define A_VHI   (2 * A_TILE)
#define A_VLO   (3 * A_TILE)
#define A_STAGE (4 * A_TILE)            // 36864 B
#define ATTN_SMEM (2 * A_TILE + 2 * A_STAGE)   // 92160 B

__device__ __forceinline__ void attn_load_kv(
    uint32_t sb, const __nv_bfloat16* __restrict__ qhi,
    const __nv_bfloat16* __restrict__ qlo, int tglob0, int h, int tid)
{
#pragma unroll
    for (int j = 0; j < 4; j++) {
        int idx = tid + j * 128;
        int r = idx >> 3, c = idx & 7;
        size_t g = (size_t)(tglob0 + r) * 3072 + h * 64 + c * 8;
        uint32_t off = (uint32_t)(r * A_LDS + c * 16);
        cp_async16(sb + A_KHI + off, qhi + g + 1024);
        cp_async16(sb + A_KLO + off, qlo + g + 1024);
        cp_async16(sb + A_VHI + off, qhi + g + 2048);
        cp_async16(sb + A_VLO + off, qlo + g + 2048);
    }
    cp_commit();
}

__global__ void __launch_bounds__(128) attn_kernel(
    const __nv_bfloat16* __restrict__ qkvhi,
    const __nv_bfloat16* __restrict__ qkvlo,
    __nv_bfloat16* __restrict__ yhi, __nv_bfloat16* __restrict__ ylo)
{
    extern __shared__ char smem[];
    const uint32_t sbase = smem_u32(smem);

    const int qb = (int)gridDim.x - 1 - (int)blockIdx.x;
    const int bh = blockIdx.y;
    const int b  = bh >> 4;
    const int h  = bh & 15;

    const int tid  = threadIdx.x;
    const int lane = tid & 31;
    const int w    = tid >> 5;            // warp: rows w*16 .. w*16+15
    const int r0   = lane >> 2;           // row in-frag (also +8)
    const int c2   = (lane & 3) * 2;      // col pair base

    const uint32_t lm_off = (uint32_t)((lane & 15) * A_LDS + (lane >> 4) * 16);
    const int q_tok0 = b * T_SEQ + qb * 64;

    // ---- prologue loads: Q tile + KV stage 0 (group 0), KV stage 1 (grp 1)
    {
#pragma unroll
        for (int j = 0; j < 4; j++) {
            int idx = tid + j * 128;
            int r = idx >> 3, c = idx & 7;
            size_t g = (size_t)(q_tok0 + r) * 3072 + h * 64 + c * 8;
            uint32_t off = (uint32_t)(r * A_LDS + c * 16);
            cp_async16(sbase + AQ_HI + off, qkvhi + g);
            cp_async16(sbase + AQ_LO + off, qkvlo + g);
        }
        attn_load_kv(sbase + A_ST0, qkvhi, qkvlo, b * T_SEQ, h, tid);  // kt=0 (same commit)
    }
    const int ktiles = qb + 1;
    if (ktiles > 1)
        attn_load_kv(sbase + A_ST0 + A_STAGE, qkvhi, qkvlo, b * T_SEQ + 64, h, tid);

    uint32_t qfhi[4][4], qflo[4][4];      // Q a-frags per kstep
    float oacc[8][4];
    float m_i[2] = {-1e30f, -1e30f};
    float l_i[2] = {0.0f, 0.0f};
#pragma unroll
    for (int dt = 0; dt < 8; dt++)
#pragma unroll
        for (int q = 0; q < 4; q++) oacc[dt][q] = 0.0f;

    for (int kt = 0; kt < ktiles; kt++) {
        const uint32_t sb = sbase + A_ST0 + (uint32_t)(kt & 1) * A_STAGE;

        if (kt < ktiles - 1) cp_wait<1>(); else cp_wait<0>();
        __syncthreads();

        if (kt == 0) {   // Q fragments resident for whole block
#pragma unroll
            for (int kk = 0; kk < 4; kk++) {
                uint32_t addr = (uint32_t)(w * 16 * A_LDS + kk * 32) + lm_off;
                ldmatrix_x4(qfhi[kk], sbase + AQ_HI + addr);
                ldmatrix_x4(qflo[kk], sbase + AQ_LO + addr);
            }
        }

        // ---- S = Q K^T (3-pass) ----
        float sacc[8][4];
#pragma unroll
        for (int nt = 0; nt < 8; nt++)
#pragma unroll
            for (int q = 0; q < 4; q++) sacc[nt][q] = 0.0f;

#pragma unroll
        for (int kk = 0; kk < 4; kk++) {
            const uint32_t kcol = (uint32_t)(kk * 32);
#pragma unroll
            for (int pair = 0; pair < 4; pair++) {
                uint32_t rh[4], rl[4];
                uint32_t addr = (uint32_t)(pair * 16 * A_LDS) + kcol + lm_off;
                ldmatrix_x4(rh, sb + A_KHI + addr);
                ldmatrix_x4(rl, sb + A_KLO + addr);
                uint32_t b0h[2] = {rh[0], rh[2]}, b1h[2] = {rh[1], rh[3]};
                uint32_t b0l[2] = {rl[0], rl[2]}, b1l[2] = {rl[1], rl[3]};
                mma_bf16(sacc[pair * 2 + 0], qfhi[kk], b0h);
                mma_bf16(sacc[pair * 2 + 1], qfhi[kk], b1h);
                mma_bf16(sacc[pair * 2 + 0], qflo[kk], b0h);
                mma_bf16(sacc[pair * 2 + 1], qflo[kk], b1h);
                mma_bf16(sacc[pair * 2 + 0], qfhi[kk], b0l);
                mma_bf16(sacc[pair * 2 + 1], qfhi[kk], b1l);
            }
        }

        // ---- scale + causal mask ----
#pragma unroll
        for (int nt = 0; nt < 8; nt++)
#pragma unroll
            for (int q = 0; q < 4; q++) sacc[nt][q] *= 0.03125f;

        if (kt == qb) {
            const int rowl0 = w * 16 + r0;
#pragma unroll
            for (int nt = 0; nt < 8; nt++) {
                int col0 = nt * 8 + c2;
                if (col0 > rowl0)     sacc[nt][0] = -1e30f;
                if (col0 + 1 > rowl0) sacc[nt][1] = -1e30f;
                if (col0 > rowl0 + 8)     sacc[nt][2] = -1e30f;
                if (col0 + 1 > rowl0 + 8) sacc[nt][3] = -1e30f;
            }
        }

        // ---- online softmax on fragments ----
        float mn[2] = {-1e30f, -1e30f};
#pragma unroll
        for (int nt = 0; nt < 8; nt++) {
            mn[0] = fmaxf(mn[0], fmaxf(sacc[nt][0], sacc[nt][1]));
            mn[1] = fmaxf(mn[1], fmaxf(sacc[nt][2], sacc[nt][3]));
        }
#pragma unroll
        for (int o = 1; o < 4; o <<= 1) {
            mn[0] = fmaxf(mn[0], __shfl_xor_sync(0xffffffffu, mn[0], o));
            mn[1] = fmaxf(mn[1], __shfl_xor_sync(0xffffffffu, mn[1], o));
        }
        float alpha[2];
#pragma unroll
        for (int q = 0; q < 2; q++) {
            float mNew = fmaxf(m_i[q], mn[q]);
            alpha[q] = __expf(m_i[q] - mNew);
            m_i[q] = mNew;
        }
        float rs[2] = {0.0f, 0.0f};
#pragma unroll
        for (int nt = 0; nt < 8; nt++) {
            sacc[nt][0] = __expf(sacc[nt][0] - m_i[0]);
            sacc[nt][1] = __expf(sacc[nt][1] - m_i[0]);
            sacc[nt][2] = __expf(sacc[nt][2] - m_i[1]);
            sacc[nt][3] = __expf(sacc[nt][3] - m_i[1]);
            rs[0] += sacc[nt][0] + sacc[nt][1];
            rs[1] += sacc[nt][2] + sacc[nt][3];
        }
#pragma unroll
        for (int o = 1; o < 4; o <<= 1) {
            rs[0] += __shfl_xor_sync(0xffffffffu, rs[0], o);
            rs[1] += __shfl_xor_sync(0xffffffffu, rs[1], o);
        }
        l_i[0] = l_i[0] * alpha[0] + rs[0];
        l_i[1] = l_i[1] * alpha[1] + rs[1];
#pragma unroll
        for (int dt = 0; dt < 8; dt++) {
            oacc[dt][0] *= alpha[0]; oacc[dt][1] *= alpha[0];
            oacc[dt][2] *= alpha[1]; oacc[dt][3] *= alpha[1];
        }

        // ---- O += P V (3-pass) ----
#pragma unroll
        for (int kk = 0; kk < 4; kk++) {
            // P a-frags from sacc of ntiles 2kk (keys 0-7) and 2kk+1 (keys 8-15)
            uint32_t phi[4], plo[4];
#pragma unroll
            for (int half = 0; half < 2; half++) {
                const float* s0 = sacc[2 * kk + half];
                __nv_bfloat162 h0 = __floats2bfloat162_rn(s0[0], s0[1]);
                __nv_bfloat162 h1 = __floats2bfloat162_rn(s0[2], s0[3]);
                __nv_bfloat162 l0 = __floats2bfloat162_rn(
                    s0[0] - __bfloat162float(h0.x), s0[1] - __bfloat162float(h0.y));
                __nv_bfloat162 l1 = __floats2bfloat162_rn(
                    s0[2] - __bfloat162float(h1.x), s0[3] - __bfloat162float(h1.y));
                phi[half * 2 + 0] = *(uint32_t*)&h0;   // rows r0,   keys half*8 + c2
                phi[half * 2 + 1] = *(uint32_t*)&h1;   // rows r0+8
                plo[half * 2 + 0] = *(uint32_t*)&l0;
                plo[half * 2 + 1] = *(uint32_t*)&l1;
            }
            const uint32_t krow = (uint32_t)(kk * 16 * A_LDS);
#pragma unroll
            for (int dp = 0; dp < 4; dp++) {
                uint32_t rh[4], rl[4];
                uint32_t addr = krow + (uint32_t)(dp * 32) + lm_off;
                ldmatrix_x4_t(rh, sb + A_VHI + addr);
                ldmatrix_x4_t(rl, sb + A_VLO + addr);
                uint32_t b0h[2] = {rh[0], rh[1]}, b1h[2] = {rh[2], rh[3]};
                uint32_t b0l[2] = {rl[0], rl[1]}, b1l[2] = {rl[2], rl[3]};
                mma_bf16(oacc[dp * 2 + 0], phi, b0h);
                mma_bf16(oacc[dp * 2 + 1], phi, b1h);
                mma_bf16(oacc[dp * 2 + 0], plo, b0h);
                mma_bf16(oacc[dp * 2 + 1], plo, b1h);
                mma_bf16(oacc[dp * 2 + 0], phi, b0l);
                mma_bf16(oacc[dp * 2 + 1], phi, b1l);
            }
        }
        __syncthreads();    // done reading stage (kt&1) before refill

        if (kt + 2 < ktiles)
            attn_load_kv(sb, qkvhi, qkvlo, b * T_SEQ + (kt + 2) * 64, h, tid);
    }

    // ---- epilogue: O /= l, emit bf16 hi/lo ----
    float inv0 = 1.0f / l_i[0];
    float inv1 = 1.0f / l_i[1];
    const int tok0 = q_tok0 + w * 16 + r0;
#pragma unroll
    for (int dt = 0; dt < 8; dt++) {
        int col = h * 64 + dt * 8 + c2;
#pragma unroll
        for (int half = 0; half < 2; half++) {
            float inv = half ? inv1 : inv0;
            float v0 = oacc[dt][half * 2 + 0] * inv;
            float v1 = oacc[dt][half * 2 + 1] * inv;
            size_t base = (size_t)(tok0 + half * 8) * NEMB + col;
            __nv_bfloat162 h2 = __floats2bfloat162_rn(v0, v1);
            __nv_bfloat162 l2 = __floats2bfloat162_rn(
                v0 - __bfloat162float(h2.x), v1 - __bfloat162float(h2.y));
            *(__nv_bfloat162*)&yhi[base] = h2;
            *(__nv_bfloat162*)&ylo[base] = l2;
        }
    }
}

// ---------------------------------------------------------------------------

extern "C" void kernel_launch(void* const* d_in, const int* in_sizes, int n_in,
                              void* d_out, int out_size)
{
    const float* x      = (const float*)d_in[0];
    const float* w_attn = (const float*)d_in[1];
    const float* w_proj = (const float*)d_in[2];
    float* out = (float*)d_out;

    void *qh_p, *ql_p, *xhi_p, *xlo_p, *yhi_p, *ylo_p, *wahi_p, *walo_p, *wphi_p, *wplo_p;
    cudaGetSymbolAddress(&qh_p,   g_qkvhi);
    cudaGetSymbolAddress(&ql_p,   g_qkvlo);
    cudaGetSymbolAddress(&xhi_p,  g_xhi);
    cudaGetSymbolAddress(&xlo_p,  g_xlo);
    cudaGetSymbolAddress(&yhi_p,  g_yhi);
    cudaGetSymbolAddress(&ylo_p,  g_ylo);
    cudaGetSymbolAddress(&wahi_p, g_wahi);
    cudaGetSymbolAddress(&walo_p, g_walo);
    cudaGetSymbolAddress(&wphi_p, g_wphi);
    cudaGetSymbolAddress(&wplo_p, g_wplo);

    __nv_bfloat16* qkvhi = (__nv_bfloat16*)qh_p;
    __nv_bfloat16* qkvlo = (__nv_bfloat16*)ql_p;
    __nv_bfloat16* xhi  = (__nv_bfloat16*)xhi_p;
    __nv_bfloat16* xlo  = (__nv_bfloat16*)xlo_p;
    __nv_bfloat16* yhi  = (__nv_bfloat16*)yhi_p;
    __nv_bfloat16* ylo  = (__nv_bfloat16*)ylo_p;
    __nv_bfloat16* wahi = (__nv_bfloat16*)wahi_p;
    __nv_bfloat16* walo = (__nv_bfloat16*)walo_p;
    __nv_bfloat16* wphi = (__nv_bfloat16*)wphi_p;
    __nv_bfloat16* wplo = (__nv_bfloat16*)wplo_p;

    cudaFuncSetAttribute(gemm_mma_kernel<0>,
                         cudaFuncAttributeMaxDynamicSharedMemorySize, GEMM_SMEM);
    cudaFuncSetAttribute(gemm_mma_kernel<1>,
                         cudaFuncAttributeMaxDynamicSharedMemorySize, GEMM_SMEM);
    cudaFuncSetAttribute(attn_kernel,
                         cudaFuncAttributeMaxDynamicSharedMemorySize, ATTN_SMEM);

    split_kernel<<<(8192 * 1024 / 4 + 255) / 256, 256>>>(x, xhi, xlo, 8192 * 1024 / 4);
    tsplit_kernel<<<dim3(3072 / 32, 1024 / 32), dim3(32, 8)>>>(w_attn, wahi, walo, 1024, 3072);
    tsplit_kernel<<<dim3(1024 / 32, 1024 / 32), dim3(32, 8)>>>(w_proj, wphi, wplo, 1024, 1024);

    // 1) qkv (bf16 hi/lo) = x @ w_attn
    gemm_mma_kernel<1><<<dim3(3072 / 128, 8192 / 128), 256, GEMM_SMEM>>>(
        xhi, xlo, wahi, walo, nullptr, qkvhi, qkvlo, 3072);

    // 2) y (bf16 hi/lo) = causal attention
    attn_kernel<<<dim3(32, 64), 128, ATTN_SMEM>>>(qkvhi, qkvlo, yhi, ylo);

    // 3) out = y @ w_proj
    gemm_mma_kernel<0><<<dim3(1024 / 128, 8192 / 128), 256, GEMM_SMEM>>>(
        yhi, ylo, wphi, wplo, out, nullptr, nullptr, 1024);
}